// round 12
// baseline (speedup 1.0000x reference)
#include <cuda_runtime.h>
#include <cuda_bf16.h>

#define HIDW 3072
#define DHW  128
#define NHW  24
#define S_ALL 1536
#define TXTN 512
#define IMGN 1024

// fp32 scratch (intermediates)
__device__ float g_buf[11520ull * 3072ull];

#define O_Q     0
#define O_K     1024
#define O_EQ    2048
#define O_EK    2560
#define O_IPK   3072
#define O_ATTN  8960
#define O_IPOUT 10496

// bf16 hi/lo arenas (flash operands only)
#define BF_TOT 110250000ull
__device__ __nv_bfloat16 g_bh[BF_TOT];
__device__ __nv_bfloat16 g_bl[BF_TOT];

#define OFF_QF    92160000ull
#define OFF_KF    96878592ull
#define OFF_VF    101597184ull
#define OFF_IPQ   106315776ull
#define OFF_IPK   109461504ull
#define OFF_IPV   109854720ull

// ---------------------------------------------------------------------------
// PTX helpers
// ---------------------------------------------------------------------------
__device__ __forceinline__ unsigned smem_u32(const void* p) {
    return (unsigned)__cvta_generic_to_shared(p);
}
__device__ __forceinline__ void cp_async16(unsigned s, const void* g) {
    asm volatile("cp.async.cg.shared.global [%0], [%1], 16;" :: "r"(s), "l"(g));
}
#define CP_COMMIT() asm volatile("cp.async.commit_group;" ::: "memory")

#define LDSM_X4(r, addr) \
    asm volatile("ldmatrix.sync.aligned.m8n8.x4.shared.b16 {%0,%1,%2,%3}, [%4];" \
                 : "=r"((r)[0]), "=r"((r)[1]), "=r"((r)[2]), "=r"((r)[3]) \
                 : "r"(addr))
#define LDSM_X4T(r, addr) \
    asm volatile("ldmatrix.sync.aligned.m8n8.x4.trans.shared.b16 {%0,%1,%2,%3}, [%4];" \
                 : "=r"((r)[0]), "=r"((r)[1]), "=r"((r)[2]), "=r"((r)[3]) \
                 : "r"(addr))

__device__ __forceinline__ void mma16816(float* c, const unsigned* a,
                                         unsigned b0, unsigned b1) {
    asm volatile(
        "mma.sync.aligned.m16n8k16.row.col.f32.bf16.bf16.f32 "
        "{%0,%1,%2,%3}, {%4,%5,%6,%7}, {%8,%9}, {%0,%1,%2,%3};"
        : "+f"(c[0]), "+f"(c[1]), "+f"(c[2]), "+f"(c[3])
        : "r"(a[0]), "r"(a[1]), "r"(a[2]), "r"(a[3]), "r"(b0), "r"(b1));
}

__device__ __forceinline__ float fex2(float x) {
    float y;
    asm("ex2.approx.f32 %0, %1;" : "=f"(y) : "f"(x));
    return y;
}
// packs (first, second) -> bf16x2 in memory order first,second
__device__ __forceinline__ unsigned pack_bf2(float a, float b) {
    unsigned r;
    asm("cvt.rn.bf16x2.f32 %0, %1, %2;" : "=r"(r) : "f"(b), "f"(a));
    return r;
}

__device__ __forceinline__ unsigned sw64(int row, int cb) {
    return (unsigned)(row * 64 + (cb ^ (((row >> 1) & 3) << 4)));
}
__device__ __forceinline__ unsigned sw256(int row, int cb) {
    return (unsigned)(row * 256 + (cb ^ ((row & 7) << 4)));
}

// ---------------------------------------------------------------------------
// Multi-job mma.sync GEMM consuming fp32 A/B via REGISTER staging.
// C[M,3072] = A[M,K] @ B[3072,K]^T + bias, bf16 hi/lo 3-pass (pass-outermost).
// Per chunk (k=32): each thread LDG.128-prefetches 16 A + 16 B fp32 elements
// into regs, converts to bf16 hi/lo in double-buffered smem (2 x 32 KB),
// ONE __syncthreads, then the R9 MMA section.
// mode 0: fp32 C out. mode 1: bf16 hi/lo out.
// ---------------------------------------------------------------------------
struct GJob {
    const float *A, *B, *bias;
    float* C;
    __nv_bfloat16 *Oh, *Ol;
    int K, blk0, mode, pad;
};
struct GJobs { GJob j[8]; int njobs; };

__global__ __launch_bounds__(256, 2) void gemm_multi_kernel(GJobs jobs)
{
    extern __shared__ char gsm[];
    const unsigned sm0 = smem_u32(gsm);        // 2 x 32 KB bf16 buffers
    const int tid = threadIdx.x;
    const int w = tid >> 5, lane = tid & 31;
    const int wm = w & 1;
    const int wn = w >> 1;

    int b = blockIdx.x;
    int ji = 0;
#pragma unroll 1
    while (ji + 1 < jobs.njobs && b >= jobs.j[ji + 1].blk0) ji++;
    const GJob J = jobs.j[ji];
    const int rem = b - J.blk0;
    const int bn = (rem % 24) * 128;
    const int bm = (rem / 24) * 128;
    const int K = J.K;

    // thread-owned gmem lanes: row = tid>>3 (+ i*32), float col = (tid&7)*4
    const float* aP = J.A + (size_t)(bm + (tid >> 3)) * K + (tid & 7) * 4;
    const float* bP = J.B + (size_t)(bn + (tid >> 3)) * K + (tid & 7) * 4;
    const size_t rstep = (size_t)32 * K;       // 32 rows

    // destination offsets in bf16 buffer (same for all chunks)
    unsigned doff[4];
#pragma unroll
    for (int i = 0; i < 4; i++) {
        int slot = i * 256 + tid;
        int row = slot >> 3, cb = (slot & 7) * 8;
        doff[i] = row * 64 + (cb ^ (((row >> 1) & 3) << 4));
    }

    const int nchunks = K >> 5;

    float acc[4][4][4];
#pragma unroll
    for (int i = 0; i < 4; i++)
#pragma unroll
        for (int j = 0; j < 4; j++)
#pragma unroll
            for (int q = 0; q < 4; q++) acc[i][j][q] = 0.f;

    // prologue: load chunk 0 into regs
    float4 rA[4], rB[4];
#pragma unroll
    for (int i = 0; i < 4; i++) {
        rA[i] = *(const float4*)(aP + i * rstep);
        rB[i] = *(const float4*)(bP + i * rstep);
    }

    for (int c = 0; c < nchunks; c++) {
        const unsigned buf = sm0 + (c & 1) * 32768;
        // convert regs -> bf16 hi/lo smem (A: 0/8192, B: 16384/24576)
#pragma unroll
        for (int i = 0; i < 4; i++) {
            float4 v = rA[i];
            unsigned h01 = pack_bf2(v.x, v.y);
            unsigned h23 = pack_bf2(v.z, v.w);
            float hx = __bfloat162float(__float2bfloat16(v.x));
            float hy = __bfloat162float(__float2bfloat16(v.y));
            float hz = __bfloat162float(__float2bfloat16(v.z));
            float hw = __bfloat162float(__float2bfloat16(v.w));
            unsigned l01 = pack_bf2(v.x - hx, v.y - hy);
            unsigned l23 = pack_bf2(v.z - hz, v.w - hw);
            asm volatile("st.shared.v2.b32 [%0], {%1,%2};"
                         :: "r"(buf + doff[i]), "r"(h01), "r"(h23) : "memory");
            asm volatile("st.shared.v2.b32 [%0], {%1,%2};"
                         :: "r"(buf + 8192 + doff[i]), "r"(l01), "r"(l23) : "memory");
            v = rB[i];
            h01 = pack_bf2(v.x, v.y);
            h23 = pack_bf2(v.z, v.w);
            hx = __bfloat162float(__float2bfloat16(v.x));
            hy = __bfloat162float(__float2bfloat16(v.y));
            hz = __bfloat162float(__float2bfloat16(v.z));
            hw = __bfloat162float(__float2bfloat16(v.w));
            l01 = pack_bf2(v.x - hx, v.y - hy);
            l23 = pack_bf2(v.z - hz, v.w - hw);
            asm volatile("st.shared.v2.b32 [%0], {%1,%2};"
                         :: "r"(buf + 16384 + doff[i]), "r"(h01), "r"(h23) : "memory");
            asm volatile("st.shared.v2.b32 [%0], {%1,%2};"
                         :: "r"(buf + 24576 + doff[i]), "r"(l01), "r"(l23) : "memory");
        }
        // prefetch next chunk into regs (in-flight during barrier + mma)
        if (c + 1 < nchunks) {
            const int ko = (c + 1) * 32;
#pragma unroll
            for (int i = 0; i < 4; i++) {
                rA[i] = *(const float4*)(aP + i * rstep + ko);
                rB[i] = *(const float4*)(bP + i * rstep + ko);
            }
        }
        __syncthreads();

        // --- R9 MMA section: passes outermost, frags reloaded per pass ---
        const unsigned aoff[3] = {0u, 0u, 8192u};          // Ah, Ah, Al
        const unsigned boff[3] = {16384u, 24576u, 16384u}; // Bh, Bl, Bh
#pragma unroll
        for (int p = 0; p < 3; p++) {
            const unsigned sA = buf + aoff[p];
            const unsigned sB = buf + boff[p];
#pragma unroll
            for (int ks = 0; ks < 2; ks++) {
                const int kb = ks * 32;
                unsigned bf[2][4];
#pragma unroll
                for (int bt = 0; bt < 2; bt++) {
                    int row = wn * 32 + bt * 16 + (lane & 7) + ((lane >> 4) << 3);
                    int cb = kb + (((lane >> 3) & 1) << 4);
                    LDSM_X4(bf[bt], sB + sw64(row, cb));
                }
#pragma unroll
                for (int mt = 0; mt < 4; mt++) {
                    unsigned af[4];
                    {
                        int row = wm * 64 + mt * 16 + (lane & 15);
                        int cb = kb + ((lane >> 4) << 4);
                        LDSM_X4(af, sA + sw64(row, cb));
                    }
#pragma unroll
                    for (int nt = 0; nt < 4; nt++)
                        mma16816(acc[mt][nt], af,
                                 bf[nt >> 1][(nt & 1) * 2],
                                 bf[nt >> 1][(nt & 1) * 2 + 1]);
                }
            }
        }
    }

    const int gq = lane >> 2, tig = lane & 3;
    if (J.mode == 0) {
#pragma unroll
        for (int mt = 0; mt < 4; mt++) {
#pragma unroll
            for (int nt = 0; nt < 4; nt++) {
                int row0 = bm + wm * 64 + mt * 16 + gq;
                int col = bn + wn * 32 + nt * 8 + tig * 2;
                float b0 = J.bias[col], b1 = J.bias[col + 1];
                *(float2*)(J.C + (size_t)row0 * HIDW + col) =
                    make_float2(acc[mt][nt][0] + b0, acc[mt][nt][1] + b1);
                *(float2*)(J.C + (size_t)(row0 + 8) * HIDW + col) =
                    make_float2(acc[mt][nt][2] + b0, acc[mt][nt][3] + b1);
            }
        }
    } else {
#pragma unroll
        for (int mt = 0; mt < 4; mt++) {
#pragma unroll
            for (int nt = 0; nt < 4; nt++) {
                int row0 = bm + wm * 64 + mt * 16 + gq;
                int col = bn + wn * 32 + nt * 8 + tig * 2;
                float b0 = J.bias[col], b1 = J.bias[col + 1];
                float v00 = acc[mt][nt][0] + b0, v01 = acc[mt][nt][1] + b1;
                float v10 = acc[mt][nt][2] + b0, v11 = acc[mt][nt][3] + b1;
                __nv_bfloat16 h00 = __float2bfloat16(v00);
                __nv_bfloat16 h01 = __float2bfloat16(v01);
                __nv_bfloat16 h10 = __float2bfloat16(v10);
                __nv_bfloat16 h11 = __float2bfloat16(v11);
                size_t o0 = (size_t)row0 * HIDW + col;
                size_t o1 = (size_t)(row0 + 8) * HIDW + col;
                *(__nv_bfloat162*)(J.Oh + o0) = __halves2bfloat162(h00, h01);
                *(__nv_bfloat162*)(J.Oh + o1) = __halves2bfloat162(h10, h11);
                *(__nv_bfloat162*)(J.Ol + o0) = __halves2bfloat162(
                    __float2bfloat16(v00 - __bfloat162float(h00)),
                    __float2bfloat16(v01 - __bfloat162float(h01)));
                *(__nv_bfloat162*)(J.Ol + o1) = __halves2bfloat162(
                    __float2bfloat16(v10 - __bfloat162float(h10)),
                    __float2bfloat16(v11 - __bfloat162float(h11)));
            }
        }
    }
}

// ---------------------------------------------------------------------------
// Flash attention on mma.sync with bf16 hi/lo 3-pass (unchanged).
// ---------------------------------------------------------------------------
#define SCL2E 0.12751743f

__device__ __forceinline__ void fa_load_stage(
    unsigned sb, const char* kh, const char* kl, const char* vh, const char* vl,
    int kv0, size_t hb, int tid)
{
    const char* srcs[4] = {kh, kl, vh, vl};
#pragma unroll
    for (int j = 0; j < 4; j++) {
#pragma unroll
        for (int i = 0; i < 4; i++) {
            int slot = i * 256 + tid;
            int row = slot >> 4, cb = (slot & 15) * 16;
            cp_async16(sb + j * 16384 + sw256(row, cb),
                       srcs[j] + (size_t)(kv0 + row) * 6144 + hb + cb);
        }
    }
    CP_COMMIT();
}

__global__ __launch_bounds__(256, 1) void flash_kernel(
    const __nv_bfloat16* __restrict__ Qh, const __nv_bfloat16* __restrict__ Ql,
    const __nv_bfloat16* __restrict__ Kh, const __nv_bfloat16* __restrict__ Kl,
    const __nv_bfloat16* __restrict__ Vh, const __nv_bfloat16* __restrict__ Vl,
    float* __restrict__ O, int nkv)
{
    extern __shared__ char fsm[];
    const unsigned sQh = smem_u32(fsm);
    const unsigned sQl = sQh + 32768;
    const unsigned sStg = sQh + 65536;
    const int tid = threadIdx.x;
    const int w = tid >> 5, lane = tid & 31;
    const int gp = lane >> 2, tig = lane & 3;
    const int h = blockIdx.y;
    const int q0 = blockIdx.x * 128;
    const int m0 = w * 16;
    const size_t hb = (size_t)h * 256;

    {
        const char* gq[2] = {(const char*)Qh, (const char*)Ql};
        const unsigned sq[2] = {sQh, sQl};
#pragma unroll
        for (int t2 = 0; t2 < 2; t2++)
#pragma unroll
            for (int i = 0; i < 8; i++) {
                int slot = i * 256 + tid;
                int row = slot >> 4, cb = (slot & 15) * 16;
                cp_async16(sq[t2] + sw256(row, cb),
                           gq[t2] + (size_t)(q0 + row) * 6144 + hb + cb);
            }
        CP_COMMIT();
    }

    const int ntile = nkv >> 6;
    fa_load_stage(sStg, (const char*)Kh, (const char*)Kl,
                  (const char*)Vh, (const char*)Vl, 0, hb, tid);

    float o[16][4];
#pragma unroll
    for (int i = 0; i < 16; i++)
#pragma unroll
        for (int j = 0; j < 4; j++) o[i][j] = 0.f;
    float m_0 = -1e30f, m_1 = -1e30f;
    float l_0 = 0.f, l_1 = 0.f;

    for (int t = 0; t < ntile; t++) {
        if (t + 1 < ntile) {
            fa_load_stage(sStg + ((t + 1) & 1) * 65536, (const char*)Kh,
                          (const char*)Kl, (const char*)Vh, (const char*)Vl,
                          (t + 1) * 64, hb, tid);
            asm volatile("cp.async.wait_group 1;" ::: "memory");
        } else {
            asm volatile("cp.async.wait_group 0;" ::: "memory");
        }
        __syncthreads();

        const unsigned sb = sStg + (t & 1) * 65536;
        const unsigned sK_h = sb, sK_l = sb + 16384;
        const unsigned sV_h = sb + 32768, sV_l = sb + 49152;

        float s[8][4];
#pragma unroll
        for (int i = 0; i < 8; i++)
#pragma unroll
            for (int j = 0; j < 4; j++) s[i][j] = 0.f;

#pragma unroll
        for (int kc = 0; kc < 8; kc++) {
            const int arow = m0 + (lane & 15);
            const int acb = kc * 32 + ((lane >> 4) << 4);
            unsigned afh[4], afl[4];
            LDSM_X4(afh, sQh + sw256(arow, acb));
            LDSM_X4(afl, sQl + sw256(arow, acb));
            const int brow = (lane & 7) + ((lane >> 4) << 3);
            const int bcb = kc * 32 + (((lane >> 3) & 1) << 4);
#pragma unroll
            for (int bt = 0; bt < 4; bt++) {
                unsigned bh_[4], bl_[4];
                LDSM_X4(bh_, sK_h + sw256(bt * 16 + brow, bcb));
                LDSM_X4(bl_, sK_l + sw256(bt * 16 + brow, bcb));
                mma16816(s[2 * bt], afh, bh_[0], bh_[1]);
                mma16816(s[2 * bt + 1], afh, bh_[2], bh_[3]);
                mma16816(s[2 * bt], afh, bl_[0], bl_[1]);
                mma16816(s[2 * bt + 1], afh, bl_[2], bl_[3]);
                mma16816(s[2 * bt], afl, bh_[0], bh_[1]);
                mma16816(s[2 * bt + 1], afl, bh_[2], bh_[3]);
            }
        }

        float mx0 = -1e30f, mx1 = -1e30f;
#pragma unroll
        for (int nt = 0; nt < 8; nt++) {
            mx0 = fmaxf(mx0, fmaxf(s[nt][0], s[nt][1]));
            mx1 = fmaxf(mx1, fmaxf(s[nt][2], s[nt][3]));
        }
        mx0 = fmaxf(mx0, __shfl_xor_sync(0xffffffffu, mx0, 1));
        mx0 = fmaxf(mx0, __shfl_xor_sync(0xffffffffu, mx0, 2));
        mx1 = fmaxf(mx1, __shfl_xor_sync(0xffffffffu, mx1, 1));
        mx1 = fmaxf(mx1, __shfl_xor_sync(0xffffffffu, mx1, 2));
        const float mn0 = fmaxf(m_0, mx0), mn1 = fmaxf(m_1, mx1);
        const float al0 = fex2((m_0 - mn0) * SCL2E);
        const float al1 = fex2((m_1 - mn1) * SCL2E);
        m_0 = mn0; m_1 = mn1;

        float sum0 = 0.f, sum1 = 0.f;
        unsigned aPh[4][4], aPl[4][4];
#pragma unroll
        for (int nt = 0; nt < 8; nt++) {
            float p0 = fex2((s[nt][0] - mn0) * SCL2E);
            float p1 = fex2((s[nt][1] - mn0) * SCL2E);
            float p2 = fex2((s[nt][2] - mn1) * SCL2E);
            float p3 = fex2((s[nt][3] - mn1) * SCL2E);
            sum0 += p0 + p1;
            sum1 += p2 + p3;
            float h0 = __bfloat162float(__float2bfloat16(p0));
            float h1 = __bfloat162float(__float2bfloat16(p1));
            float h2 = __bfloat162float(__float2bfloat16(p2));
            float h3 = __bfloat162float(__float2bfloat16(p3));
            const int kc = nt >> 1, hf = (nt & 1) * 2;
            aPh[kc][hf] = pack_bf2(p0, p1);
            aPh[kc][hf + 1] = pack_bf2(p2, p3);
            aPl[kc][hf] = pack_bf2(p0 - h0, p1 - h1);
            aPl[kc][hf + 1] = pack_bf2(p2 - h2, p3 - h3);
        }
        sum0 += __shfl_xor_sync(0xffffffffu, sum0, 1);
        sum0 += __shfl_xor_sync(0xffffffffu, sum0, 2);
        sum1 += __shfl_xor_sync(0xffffffffu, sum1, 1);
        sum1 += __shfl_xor_sync(0xffffffffu, sum1, 2);
        l_0 = l_0 * al0 + sum0;
        l_1 = l_1 * al1 + sum1;

#pragma unroll
        for (int i = 0; i < 16; i++) {
            o[i][0] *= al0; o[i][1] *= al0;
            o[i][2] *= al1; o[i][3] *= al1;
        }

        const int vrow0 = (lane & 7) + (((lane >> 3) & 1) << 3);
        const int vcbl = (lane >> 4) << 4;
#pragma unroll
        for (int kc = 0; kc < 4; kc++) {
            const int vr = kc * 16 + vrow0;
#pragma unroll
            for (int nb = 0; nb < 8; nb++) {
                unsigned vh_[4], vl_[4];
                const int vcb = nb * 32 + vcbl;
                LDSM_X4T(vh_, sV_h + sw256(vr, vcb));
                LDSM_X4T(vl_, sV_l + sw256(vr, vcb));
                mma16816(o[2 * nb], aPh[kc], vh_[0], vh_[1]);
                mma16816(o[2 * nb + 1], aPh[kc], vh_[2], vh_[3]);
                mma16816(o[2 * nb], aPh[kc], vl_[0], vl_[1]);
                mma16816(o[2 * nb + 1], aPh[kc], vl_[2], vl_[3]);
                mma16816(o[2 * nb], aPl[kc], vh_[0], vh_[1]);
                mma16816(o[2 * nb + 1], aPl[kc], vh_[2], vh_[3]);
            }
        }
        __syncthreads();
    }

    const float inv0 = 1.0f / l_0, inv1 = 1.0f / l_1;
    const int row0 = q0 + m0 + gp;
#pragma unroll
    for (int nt = 0; nt < 16; nt++) {
        const int col = h * 128 + nt * 8 + tig * 2;
        *(float2*)(O + (size_t)row0 * HIDW + col) =
            make_float2(o[nt][0] * inv0, o[nt][1] * inv0);
        *(float2*)(O + (size_t)(row0 + 8) * HIDW + col) =
            make_float2(o[nt][2] * inv1, o[nt][3] * inv1);
    }
}

// ---------------------------------------------------------------------------
// Fused rms + rope + bf16-split: warp-per-head, thread-owns-4-dims.
// grid 4224 blocks x 256 threads. No barriers.
// ---------------------------------------------------------------------------
__global__ __launch_bounds__(256) void fuse_qk_kernel(
    const float* __restrict__ Qb, const float* __restrict__ Kb,
    const float* __restrict__ EQb, const float* __restrict__ EKb,
    const float* __restrict__ IPKb,
    const float* __restrict__ nqw, const float* __restrict__ nkw,
    const float* __restrict__ naqw, const float* __restrict__ nakw,
    const float* __restrict__ nipq, const float* __restrict__ nipk,
    const float* __restrict__ cosT, const float* __restrict__ sinT,
    __nv_bfloat16* __restrict__ bh, __nv_bfloat16* __restrict__ bl)
{
    const int r = blockIdx.x;
    const int w = threadIdx.x >> 5, lane = threadIdx.x & 31;

    const float* src;
    const float* wv;
    size_t obase;
    int row_out;
    bool do_rope;

    if (r < 1536) {
        row_out = r; do_rope = true; obase = OFF_QF;
        if (r < 512) { src = EQb + (size_t)r * HIDW; wv = naqw; }
        else         { src = Qb + (size_t)(r - 512) * HIDW; wv = nqw; }
    } else if (r < 3072) {
        row_out = r - 1536; do_rope = true; obase = OFF_KF;
        if (row_out < 512) { src = EKb + (size_t)row_out * HIDW; wv = nakw; }
        else               { src = Kb + (size_t)(row_out - 512) * HIDW; wv = nkw; }
    } else if (r < 4096) {
        row_out = r - 3072; do_rope = false; obase = OFF_IPQ;
        src = Qb + (size_t)row_out * HIDW; wv = nipq;
    } else {
        row_out = r - 4096; do_rope = false; obase = OFF_IPK;
        src = IPKb + (size_t)row_out * HIDW; wv = nipk;
    }

    const int d4 = lane * 4;
    const float4 wvv = *(const float4*)(wv + d4);
    float4 cs = make_float4(0, 0, 0, 0), sn = cs;
    if (do_rope) {
        cs = *(const float4*)(cosT + row_out * DHW + d4);
        sn = *(const float4*)(sinT + row_out * DHW + d4);
    }
    obase += (size_t)row_out * HIDW + d4;

#pragma unroll
    for (int hi = 0; hi < 3; hi++) {
        const int h = hi * 8 + w;
        float4 x = *(const float4*)(src + h * DHW + d4);
        float v = x.x * x.x + x.y * x.y + x.z * x.z + x.w * x.w;
#pragma unroll
        for (int off = 16; off > 0; off >>= 1)
            v += __shfl_xor_sync(0xffffffffu, v, off);
        const float rinv = rsqrtf(v * (1.0f / 128.0f) + 1e-6f);
        float y0 = x.x * rinv * wvv.x;
        float y1 = x.y * rinv * wvv.y;
        float y2 = x.z * rinv * wvv.z;
        float y3 = x.w * rinv * wvv.w;
        if (do_rope) {
            float r0 = y0 * cs.x - y1 * sn.x;
            float r1 = y1 * cs.y + y0 * sn.y;
            float r2 = y2 * cs.z - y3 * sn.z;
            float r3 = y3 * cs.w + y2 * sn.w;
            y0 = r0; y1 = r1; y2 = r2; y3 = r3;
        }
        unsigned h01 = pack_bf2(y0, y1);
        unsigned h23 = pack_bf2(y2, y3);
        float f0 = __bfloat162float(__float2bfloat16(y0));
        float f1 = __bfloat162float(__float2bfloat16(y1));
        float f2 = __bfloat162float(__float2bfloat16(y2));
        float f3 = __bfloat162float(__float2bfloat16(y3));
        unsigned l01 = pack_bf2(y0 - f0, y1 - f1);
        unsigned l23 = pack_bf2(y2 - f2, y3 - f3);
        *(uint2*)(bh + obase + h * DHW) = make_uint2(h01, h23);
        *(uint2*)(bl + obase + h * DHW) = make_uint2(l01, l23);
    }
}

// ---------------------------------------------------------------------------
// maskadd in place on fp32 attention output (bbox only). grid 256, block 256.
// ---------------------------------------------------------------------------
__global__ __launch_bounds__(256) void maskadd_kernel(
    float* __restrict__ Aimg, const float* __restrict__ IPO)
{
    const int bi = blockIdx.x;                 // 0..255 within bbox
    const int y = 8 + (bi >> 4), x = 8 + (bi & 15);
    const int i = y * 32 + x;
    float* a = Aimg + (size_t)i * HIDW;
    const float* p = IPO + (size_t)i * HIDW;
#pragma unroll
    for (int c = 0; c < HIDW / 256; c++)
        a[c * 256 + threadIdx.x] += p[c * 256 + threadIdx.x];
}

// ---------------------------------------------------------------------------
extern "C" void kernel_launch(void* const* d_in, const int* in_sizes, int n_in,
                              void* d_out, int out_size)
{
    const float* hs    = (const float*)d_in[0];
    const float* enc   = (const float*)d_in[1];
    const float* ip    = (const float*)d_in[2];
    const float* cosT  = (const float*)d_in[3];
    const float* sinT  = (const float*)d_in[4];
    const float* Wq    = (const float*)d_in[5];
    const float* bq    = (const float*)d_in[6];
    const float* Wk    = (const float*)d_in[7];
    const float* bk    = (const float*)d_in[8];
    const float* Wv    = (const float*)d_in[9];
    const float* bv    = (const float*)d_in[10];
    const float* nqw   = (const float*)d_in[11];
    const float* nkw   = (const float*)d_in[12];
    const float* Wqa   = (const float*)d_in[13];
    const float* bqa   = (const float*)d_in[14];
    const float* Wka   = (const float*)d_in[15];
    const float* bka   = (const float*)d_in[16];
    const float* Wva   = (const float*)d_in[17];
    const float* bva   = (const float*)d_in[18];
    const float* naqw  = (const float*)d_in[19];
    const float* nakw  = (const float*)d_in[20];
    const float* Wout  = (const float*)d_in[21];
    const float* bout  = (const float*)d_in[22];
    const float* Waout = (const float*)d_in[23];
    const float* baout = (const float*)d_in[24];
    const float* Wkip  = (const float*)d_in[25];
    const float* bkip  = (const float*)d_in[26];
    const float* Wvip  = (const float*)d_in[27];
    const float* bvip  = (const float*)d_in[28];
    const float* nipq  = (const float*)d_in[29];
    const float* nipk  = (const float*)d_in[30];

    float* buf = nullptr;
    cudaGetSymbolAddress((void**)&buf, g_buf);
    __nv_bfloat16* bh = nullptr;
    __nv_bfloat16* bl = nullptr;
    cudaGetSymbolAddress((void**)&bh, g_bh);
    cudaGetSymbolAddress((void**)&bl, g_bl);

    float* Qb   = buf + (size_t)O_Q * HIDW;
    float* Kb   = buf + (size_t)O_K * HIDW;
    float* EQb  = buf + (size_t)O_EQ * HIDW;
    float* EKb  = buf + (size_t)O_EK * HIDW;
    float* IPKb = buf + (size_t)O_IPK * HIDW;
    float* ATb  = buf + (size_t)O_ATTN * HIDW;
    float* IPOb = buf + (size_t)O_IPOUT * HIDW;

    float* out_img = (float*)d_out;
    float* out_enc = (float*)d_out + (size_t)IMGN * HIDW;

    const int smem_gemm = 65536;
    const int smem_fa   = 196608;
    cudaFuncSetAttribute(gemm_multi_kernel, cudaFuncAttributeMaxDynamicSharedMemorySize,
                         smem_gemm);
    cudaFuncSetAttribute(flash_kernel, cudaFuncAttributeMaxDynamicSharedMemorySize,
                         smem_fa);

    // ---- 1) all 8 projections in one GEMM launch (fp32 inputs directly) ----
    {
        GJobs gj;
        gj.njobs = 8;
        auto setj = [&](int i, const float* A, const float* B, const float* bias,
                        float* C, __nv_bfloat16* Oh, __nv_bfloat16* Ol,
                        int M, int K, int& blk) {
            gj.j[i].A = A; gj.j[i].B = B; gj.j[i].bias = bias;
            gj.j[i].C = C; gj.j[i].Oh = Oh; gj.j[i].Ol = Ol;
            gj.j[i].K = K; gj.j[i].blk0 = blk;
            gj.j[i].mode = (Oh != nullptr) ? 1 : 0;
            blk += (M / 128) * 24;
        };
        int blk = 0;
        setj(0, hs, Wq, bq, Qb, nullptr, nullptr, IMGN, HIDW, blk);
        setj(1, hs, Wk, bk, Kb, nullptr, nullptr, IMGN, HIDW, blk);
        setj(2, hs, Wv, bv, nullptr,
             bh + OFF_VF + (size_t)TXTN * HIDW, bl + OFF_VF + (size_t)TXTN * HIDW,
             IMGN, HIDW, blk);
        setj(3, enc, Wqa, bqa, EQb, nullptr, nullptr, TXTN, HIDW, blk);
        setj(4, enc, Wka, bka, EKb, nullptr, nullptr, TXTN, HIDW, blk);
        setj(5, enc, Wva, bva, nullptr,
             bh + OFF_VF, bl + OFF_VF, TXTN, HIDW, blk);
        setj(6, ip, Wkip, bkip, IPKb, nullptr, nullptr, 128, 1152, blk);
        setj(7, ip, Wvip, bvip, nullptr,
             bh + OFF_IPV, bl + OFF_IPV, 128, 1152, blk);
        gemm_multi_kernel<<<blk, 256, smem_gemm>>>(gj);
    }

    // ---- 2) fused rms + rope + split ----
    fuse_qk_kernel<<<4224, 256>>>(
        Qb, Kb, EQb, EKb, IPKb, nqw, nkw, naqw, nakw, nipq, nipk,
        cosT, sinT, bh, bl);

    // ---- 3) flash attention ----
    flash_kernel<<<dim3(S_ALL / 128, NHW), 256, smem_fa>>>(
        bh + OFF_QF, bl + OFF_QF, bh + OFF_KF, bl + OFF_KF,
        bh + OFF_VF, bl + OFF_VF, ATb, S_ALL);
    flash_kernel<<<dim3(IMGN / 128, NHW), 256, smem_fa>>>(
        bh + OFF_IPQ, bl + OFF_IPQ, bh + OFF_IPK, bl + OFF_IPK,
        bh + OFF_IPV, bl + OFF_IPV, IPOb, 128);

    // ---- 4) maskadd in place on img rows of ATb ----
    maskadd_kernel<<<256, 256>>>(ATb + (size_t)TXTN * HIDW, IPOb);

    // ---- 5) output projections in one GEMM launch (fp32 A from ATb) ----
    {
        GJobs gj;
        gj.njobs = 2;
        int blk = 0;
        gj.j[0].A = ATb + (size_t)TXTN * HIDW; gj.j[0].B = Wout;
        gj.j[0].bias = bout; gj.j[0].C = out_img;
        gj.j[0].Oh = nullptr; gj.j[0].Ol = nullptr;
        gj.j[0].K = HIDW; gj.j[0].blk0 = blk; gj.j[0].mode = 0;
        blk += (IMGN / 128) * 24;
        gj.j[1].A = ATb; gj.j[1].B = Waout;
        gj.j[1].bias = baout; gj.j[1].C = out_enc;
        gj.j[1].Oh = nullptr; gj.j[1].Ol = nullptr;
        gj.j[1].K = HIDW; gj.j[1].blk0 = blk; gj.j[1].mode = 0;
        blk += (TXTN / 128) * 24;
        gemm_multi_kernel<<<blk, 256, smem_gemm>>>(gj);
    }
}

// round 16
// speedup vs baseline: 1.2650x; 1.2650x over previous
#include <cuda_runtime.h>
#include <cuda_bf16.h>

#define HIDW 3072
#define DHW  128
#define NHW  24
#define S_ALL 1536
#define TXTN 512
#define IMGN 1024

// fp32 scratch (intermediates)
__device__ float g_buf[11520ull * 3072ull];

#define O_Q     0
#define O_K     1024
#define O_EQ    2048
#define O_EK    2560
#define O_IPK   3072
#define O_ATTN  8960
#define O_IPOUT 10496

// bf16 hi/lo arenas
#define BF_TOT 110250000ull
__device__ __nv_bfloat16 g_bh[BF_TOT];
__device__ __nv_bfloat16 g_bl[BF_TOT];

// activation splits (low region)
#define OFF_HS    0ull
#define OFF_ENC   3145728ull
#define OFF_IP    4718592ull
#define OFF_ATI   4866048ull
#define OFF_ATE   8011776ull
// flash operands (high region)
#define OFF_QF    92160000ull
#define OFF_KF    96878592ull
#define OFF_VF    101597184ull
#define OFF_IPQ   106315776ull
#define OFF_IPK   109461504ull
#define OFF_IPV   109854720ull

// ---------------------------------------------------------------------------
// PTX helpers
// ---------------------------------------------------------------------------
__device__ __forceinline__ unsigned smem_u32(const void* p) {
    return (unsigned)__cvta_generic_to_shared(p);
}
__device__ __forceinline__ void cp_async16(unsigned s, const void* g) {
    asm volatile("cp.async.cg.shared.global [%0], [%1], 16;" :: "r"(s), "l"(g));
}
#define CP_COMMIT() asm volatile("cp.async.commit_group;" ::: "memory")

#define LDSM_X4(r, addr) \
    asm volatile("ldmatrix.sync.aligned.m8n8.x4.shared.b16 {%0,%1,%2,%3}, [%4];" \
                 : "=r"((r)[0]), "=r"((r)[1]), "=r"((r)[2]), "=r"((r)[3]) \
                 : "r"(addr))
#define LDSM_X4T(r, addr) \
    asm volatile("ldmatrix.sync.aligned.m8n8.x4.trans.shared.b16 {%0,%1,%2,%3}, [%4];" \
                 : "=r"((r)[0]), "=r"((r)[1]), "=r"((r)[2]), "=r"((r)[3]) \
                 : "r"(addr))

__device__ __forceinline__ void mma16816(float* c, const unsigned* a,
                                         unsigned b0, unsigned b1) {
    asm volatile(
        "mma.sync.aligned.m16n8k16.row.col.f32.bf16.bf16.f32 "
        "{%0,%1,%2,%3}, {%4,%5,%6,%7}, {%8,%9}, {%0,%1,%2,%3};"
        : "+f"(c[0]), "+f"(c[1]), "+f"(c[2]), "+f"(c[3])
        : "r"(a[0]), "r"(a[1]), "r"(a[2]), "r"(a[3]), "r"(b0), "r"(b1));
}

__device__ __forceinline__ float fex2(float x) {
    float y;
    asm("ex2.approx.f32 %0, %1;" : "=f"(y) : "f"(x));
    return y;
}
// packs (first, second) -> bf16x2 in memory order first,second
__device__ __forceinline__ unsigned pack_bf2(float a, float b) {
    unsigned r;
    asm("cvt.rn.bf16x2.f32 %0, %1, %2;" : "=r"(r) : "f"(b), "f"(a));
    return r;
}

__device__ __forceinline__ unsigned sw64(int row, int cb) {
    return (unsigned)(row * 64 + (cb ^ (((row >> 1) & 3) << 4)));
}
__device__ __forceinline__ unsigned sw256(int row, int cb) {
    return (unsigned)(row * 256 + (cb ^ ((row & 7) << 4)));
}

// ---------------------------------------------------------------------------
// Multi-job split: fp32 -> bf16 hi + lo (activations only, proven in R8).
// ---------------------------------------------------------------------------
struct SJob { const float4* src; __nv_bfloat162* hi; __nv_bfloat162* lo; int blk0; };
struct SJobs { SJob j[4]; int njobs; };

__global__ __launch_bounds__(256) void split_multi_kernel(SJobs jobs)
{
    int b = blockIdx.x;
    int ji = 0;
#pragma unroll 1
    while (ji + 1 < jobs.njobs && b >= jobs.j[ji + 1].blk0) ji++;
    const SJob J = jobs.j[ji];
    int i = (b - J.blk0) * 256 + threadIdx.x;
    float4 v = J.src[i];
    __nv_bfloat16 h0 = __float2bfloat16(v.x);
    __nv_bfloat16 h1 = __float2bfloat16(v.y);
    __nv_bfloat16 h2 = __float2bfloat16(v.z);
    __nv_bfloat16 h3 = __float2bfloat16(v.w);
    __nv_bfloat16 l0 = __float2bfloat16(v.x - __bfloat162float(h0));
    __nv_bfloat16 l1 = __float2bfloat16(v.y - __bfloat162float(h1));
    __nv_bfloat16 l2 = __float2bfloat16(v.z - __bfloat162float(h2));
    __nv_bfloat16 l3 = __float2bfloat16(v.w - __bfloat162float(h3));
    J.hi[2 * i]     = __halves2bfloat162(h0, h1);
    J.hi[2 * i + 1] = __halves2bfloat162(h2, h3);
    J.lo[2 * i]     = __halves2bfloat162(l0, l1);
    J.lo[2 * i + 1] = __halves2bfloat162(l2, l3);
}

// ---------------------------------------------------------------------------
// Multi-job mma.sync GEMM: A pre-split bf16 (hi/lo), B fp32 + in-kernel convert.
// C[M,3072] = A[M,K] @ B[3072,K]^T + bias, bf16x3 3-pass (pass-outermost, R9).
// smem: A bf16 stages (3 x 16 KB: Ah|Al) + B fp32 stages (2 x 16 KB)
//       + B bf16 buf (16 KB: Bh|Bl) = 96 KB. 2 CTA/SM.
// mode 0: fp32 C out. mode 1: bf16 hi/lo out.
// ---------------------------------------------------------------------------
struct GJob {
    const __nv_bfloat16 *Ah, *Al;
    const float *B, *bias;
    float* C;
    __nv_bfloat16 *Oh, *Ol;
    int K, blk0, mode, pad;
};
struct GJobs { GJob j[8]; int njobs; };

// load one chunk: A bf16 hi/lo (16 KB) + B fp32 (16 KB), one commit group
__device__ __forceinline__ void gload(
    unsigned sA, unsigned sBf,
    const __nv_bfloat16* a_h, const __nv_bfloat16* a_l, const float* b_f,
    int K, int k0, int tid)
{
    // A: 2 srcs x 2 iters; slot 0..511 -> row=slot>>2, cb=(slot&3)*16
    const __nv_bfloat16* asrc[2] = {a_h + k0, a_l + k0};
#pragma unroll
    for (int j = 0; j < 2; j++) {
        const __nv_bfloat16* g = asrc[j];
#pragma unroll
        for (int i = 0; i < 2; i++) {
            int slot = i * 256 + tid;
            int row = slot >> 2;
            int cb = (slot & 3) * 16;
            cp_async16(sA + j * 8192 + sw64(row, cb),
                       (const char*)g + (size_t)row * K * 2 + cb);
        }
    }
    // B fp32: 4 iters; slot 0..1023 -> row=slot>>3, c16=slot&7
    {
        const float* g = b_f + k0;
#pragma unroll
        for (int i = 0; i < 4; i++) {
            int slot = i * 256 + tid;
            int row = slot >> 3, c16 = slot & 7;
            unsigned off = row * 128 + ((c16 * 16) ^ ((row & 1) << 6));
            cp_async16(sBf + off, (const char*)g + (size_t)row * K * 4 + c16 * 16);
        }
    }
    CP_COMMIT();
}

// convert B fp32 stage -> bf16 hi/lo buf
__device__ __forceinline__ void gconvertB(unsigned sBf, unsigned buf, int tid)
{
#pragma unroll
    for (int i = 0; i < 4; i++) {
        int slot = i * 256 + tid;
        int row = slot >> 3, c16 = slot & 7;
        unsigned soff = sBf + row * 128 + ((c16 * 16) ^ ((row & 1) << 6));
        float4 v;
        asm volatile("ld.shared.v4.f32 {%0,%1,%2,%3}, [%4];"
                     : "=f"(v.x), "=f"(v.y), "=f"(v.z), "=f"(v.w)
                     : "r"(soff));
        unsigned h01 = pack_bf2(v.x, v.y);
        unsigned h23 = pack_bf2(v.z, v.w);
        float hx = __bfloat162float(__float2bfloat16(v.x));
        float hy = __bfloat162float(__float2bfloat16(v.y));
        float hz = __bfloat162float(__float2bfloat16(v.z));
        float hw = __bfloat162float(__float2bfloat16(v.w));
        unsigned l01 = pack_bf2(v.x - hx, v.y - hy);
        unsigned l23 = pack_bf2(v.z - hz, v.w - hw);
        unsigned doff = row * 64 + ((c16 * 8) ^ (((row >> 1) & 3) << 4));
        asm volatile("st.shared.v2.b32 [%0], {%1,%2};"
                     :: "r"(buf + doff), "r"(h01), "r"(h23) : "memory");
        asm volatile("st.shared.v2.b32 [%0], {%1,%2};"
                     :: "r"(buf + 8192 + doff), "r"(l01), "r"(l23) : "memory");
    }
}

__global__ __launch_bounds__(256, 2) void gemm_multi_kernel(GJobs jobs)
{
    extern __shared__ char gsm[];
    const unsigned sm0 = smem_u32(gsm);
    // layout: A stages 0/16K/32K (each Ah|Al 8K+8K); Bf32 48K/64K; Bbuf 80K
    const unsigned sBf0 = sm0 + 49152, sBf1 = sm0 + 65536;
    const unsigned bufb = sm0 + 81920;
    const int tid = threadIdx.x;
    const int w = tid >> 5, lane = tid & 31;
    const int wm = w & 1;
    const int wn = w >> 1;

    int b = blockIdx.x;
    int ji = 0;
#pragma unroll 1
    while (ji + 1 < jobs.njobs && b >= jobs.j[ji + 1].blk0) ji++;
    const GJob J = jobs.j[ji];
    const int rem = b - J.blk0;
    const int bn = (rem % 24) * 128;
    const int bm = (rem / 24) * 128;
    const int K = J.K;

    const __nv_bfloat16* a_h = J.Ah + (size_t)bm * K;
    const __nv_bfloat16* a_l = J.Al + (size_t)bm * K;
    const float* b_f = J.B + (size_t)bn * K;

    const int nchunks = K >> 5;

    float acc[4][4][4];
#pragma unroll
    for (int i = 0; i < 4; i++)
#pragma unroll
        for (int j = 0; j < 4; j++)
#pragma unroll
            for (int q = 0; q < 4; q++) acc[i][j][q] = 0.f;

    // prologue: chunks 0 and 1
    gload(sm0, sBf0, a_h, a_l, b_f, K, 0, tid);
    gload(sm0 + 16384, sBf1, a_h, a_l, b_f, K, 32, tid);

    int astg = 0;  // A stage index for chunk c = c % 3
    for (int c = 0; c < nchunks; c++) {
        if (c + 1 < nchunks)
            asm volatile("cp.async.wait_group 1;" ::: "memory");
        else
            asm volatile("cp.async.wait_group 0;" ::: "memory");
        __syncthreads();                    // stage visible + prev mma done w/ buf
        gconvertB((c & 1) ? sBf1 : sBf0, bufb, tid);
        __syncthreads();
        if (c + 2 < nchunks) {
            int nst = astg + 2; if (nst >= 3) nst -= 3;   // (c+2) % 3
            gload(sm0 + nst * 16384, (c & 1) ? sBf1 : sBf0,
                  a_h, a_l, b_f, K, (c + 2) << 5, tid);
        }

        // --- R9 MMA section: passes outermost ---
        const unsigned sAbase = sm0 + astg * 16384;
        const unsigned aoff[3] = {0u, 0u, 8192u};    // Ah, Ah, Al
        const unsigned boff[3] = {0u, 8192u, 0u};    // Bh, Bl, Bh
#pragma unroll
        for (int p = 0; p < 3; p++) {
            const unsigned sA = sAbase + aoff[p];
            const unsigned sB = bufb + boff[p];
#pragma unroll
            for (int ks = 0; ks < 2; ks++) {
                const int kb = ks * 32;
                unsigned bf[2][4];
#pragma unroll
                for (int bt = 0; bt < 2; bt++) {
                    int row = wn * 32 + bt * 16 + (lane & 7) + ((lane >> 4) << 3);
                    int cb = kb + (((lane >> 3) & 1) << 4);
                    LDSM_X4(bf[bt], sB + sw64(row, cb));
                }
#pragma unroll
                for (int mt = 0; mt < 4; mt++) {
                    unsigned af[4];
                    {
                        int row = wm * 64 + mt * 16 + (lane & 15);
                        int cb = kb + ((lane >> 4) << 4);
                        LDSM_X4(af, sA + sw64(row, cb));
                    }
#pragma unroll
                    for (int nt = 0; nt < 4; nt++)
                        mma16816(acc[mt][nt], af,
                                 bf[nt >> 1][(nt & 1) * 2],
                                 bf[nt >> 1][(nt & 1) * 2 + 1]);
                }
            }
        }
        if (++astg == 3) astg = 0;
    }

    const int gq = lane >> 2, tig = lane & 3;
    if (J.mode == 0) {
#pragma unroll
        for (int mt = 0; mt < 4; mt++) {
#pragma unroll
            for (int nt = 0; nt < 4; nt++) {
                int row0 = bm + wm * 64 + mt * 16 + gq;
                int col = bn + wn * 32 + nt * 8 + tig * 2;
                float b0 = J.bias[col], b1 = J.bias[col + 1];
                *(float2*)(J.C + (size_t)row0 * HIDW + col) =
                    make_float2(acc[mt][nt][0] + b0, acc[mt][nt][1] + b1);
                *(float2*)(J.C + (size_t)(row0 + 8) * HIDW + col) =
                    make_float2(acc[mt][nt][2] + b0, acc[mt][nt][3] + b1);
            }
        }
    } else {
#pragma unroll
        for (int mt = 0; mt < 4; mt++) {
#pragma unroll
            for (int nt = 0; nt < 4; nt++) {
                int row0 = bm + wm * 64 + mt * 16 + gq;
                int col = bn + wn * 32 + nt * 8 + tig * 2;
                float b0 = J.bias[col], b1 = J.bias[col + 1];
                float v00 = acc[mt][nt][0] + b0, v01 = acc[mt][nt][1] + b1;
                float v10 = acc[mt][nt][2] + b0, v11 = acc[mt][nt][3] + b1;
                __nv_bfloat16 h00 = __float2bfloat16(v00);
                __nv_bfloat16 h01 = __float2bfloat16(v01);
                __nv_bfloat16 h10 = __float2bfloat16(v10);
                __nv_bfloat16 h11 = __float2bfloat16(v11);
                size_t o0 = (size_t)row0 * HIDW + col;
                size_t o1 = (size_t)(row0 + 8) * HIDW + col;
                *(__nv_bfloat162*)(J.Oh + o0) = __halves2bfloat162(h00, h01);
                *(__nv_bfloat162*)(J.Oh + o1) = __halves2bfloat162(h10, h11);
                *(__nv_bfloat162*)(J.Ol + o0) = __halves2bfloat162(
                    __float2bfloat16(v00 - __bfloat162float(h00)),
                    __float2bfloat16(v01 - __bfloat162float(h01)));
                *(__nv_bfloat162*)(J.Ol + o1) = __halves2bfloat162(
                    __float2bfloat16(v10 - __bfloat162float(h10)),
                    __float2bfloat16(v11 - __bfloat162float(h11)));
            }
        }
    }
}

// ---------------------------------------------------------------------------
// Flash attention on mma.sync with bf16 hi/lo 3-pass (unchanged).
// ---------------------------------------------------------------------------
#define SCL2E 0.12751743f

__device__ __forceinline__ void fa_load_stage(
    unsigned sb, const char* kh, const char* kl, const char* vh, const char* vl,
    int kv0, size_t hb, int tid)
{
    const char* srcs[4] = {kh, kl, vh, vl};
#pragma unroll
    for (int j = 0; j < 4; j++) {
#pragma unroll
        for (int i = 0; i < 4; i++) {
            int slot = i * 256 + tid;
            int row = slot >> 4, cb = (slot & 15) * 16;
            cp_async16(sb + j * 16384 + sw256(row, cb),
                       srcs[j] + (size_t)(kv0 + row) * 6144 + hb + cb);
        }
    }
    CP_COMMIT();
}

__global__ __launch_bounds__(256, 1) void flash_kernel(
    const __nv_bfloat16* __restrict__ Qh, const __nv_bfloat16* __restrict__ Ql,
    const __nv_bfloat16* __restrict__ Kh, const __nv_bfloat16* __restrict__ Kl,
    const __nv_bfloat16* __restrict__ Vh, const __nv_bfloat16* __restrict__ Vl,
    float* __restrict__ O, int nkv)
{
    extern __shared__ char fsm[];
    const unsigned sQh = smem_u32(fsm);
    const unsigned sQl = sQh + 32768;
    const unsigned sStg = sQh + 65536;
    const int tid = threadIdx.x;
    const int w = tid >> 5, lane = tid & 31;
    const int gp = lane >> 2, tig = lane & 3;
    const int h = blockIdx.y;
    const int q0 = blockIdx.x * 128;
    const int m0 = w * 16;
    const size_t hb = (size_t)h * 256;

    {
        const char* gq[2] = {(const char*)Qh, (const char*)Ql};
        const unsigned sq[2] = {sQh, sQl};
#pragma unroll
        for (int t2 = 0; t2 < 2; t2++)
#pragma unroll
            for (int i = 0; i < 8; i++) {
                int slot = i * 256 + tid;
                int row = slot >> 4, cb = (slot & 15) * 16;
                cp_async16(sq[t2] + sw256(row, cb),
                           gq[t2] + (size_t)(q0 + row) * 6144 + hb + cb);
            }
        CP_COMMIT();
    }

    const int ntile = nkv >> 6;
    fa_load_stage(sStg, (const char*)Kh, (const char*)Kl,
                  (const char*)Vh, (const char*)Vl, 0, hb, tid);

    float o[16][4];
#pragma unroll
    for (int i = 0; i < 16; i++)
#pragma unroll
        for (int j = 0; j < 4; j++) o[i][j] = 0.f;
    float m_0 = -1e30f, m_1 = -1e30f;
    float l_0 = 0.f, l_1 = 0.f;

    for (int t = 0; t < ntile; t++) {
        if (t + 1 < ntile) {
            fa_load_stage(sStg + ((t + 1) & 1) * 65536, (const char*)Kh,
                          (const char*)Kl, (const char*)Vh, (const char*)Vl,
                          (t + 1) * 64, hb, tid);
            asm volatile("cp.async.wait_group 1;" ::: "memory");
        } else {
            asm volatile("cp.async.wait_group 0;" ::: "memory");
        }
        __syncthreads();

        const unsigned sb = sStg + (t & 1) * 65536;
        const unsigned sK_h = sb, sK_l = sb + 16384;
        const unsigned sV_h = sb + 32768, sV_l = sb + 49152;

        float s[8][4];
#pragma unroll
        for (int i = 0; i < 8; i++)
#pragma unroll
            for (int j = 0; j < 4; j++) s[i][j] = 0.f;

#pragma unroll
        for (int kc = 0; kc < 8; kc++) {
            const int arow = m0 + (lane & 15);
            const int acb = kc * 32 + ((lane >> 4) << 4);
            unsigned afh[4], afl[4];
            LDSM_X4(afh, sQh + sw256(arow, acb));
            LDSM_X4(afl, sQl + sw256(arow, acb));
            const int brow = (lane & 7) + ((lane >> 4) << 3);
            const int bcb = kc * 32 + (((lane >> 3) & 1) << 4);
#pragma unroll
            for (int bt = 0; bt < 4; bt++) {
                unsigned bh_[4], bl_[4];
                LDSM_X4(bh_, sK_h + sw256(bt * 16 + brow, bcb));
                LDSM_X4(bl_, sK_l + sw256(bt * 16 + brow, bcb));
                mma16816(s[2 * bt], afh, bh_[0], bh_[1]);
                mma16816(s[2 * bt + 1], afh, bh_[2], bh_[3]);
                mma16816(s[2 * bt], afh, bl_[0], bl_[1]);
                mma16816(s[2 * bt + 1], afh, bl_[2], bl_[3]);
                mma16816(s[2 * bt], afl, bh_[0], bh_[1]);
                mma16816(s[2 * bt + 1], afl, bh_[2], bh_[3]);
            }
        }

        float mx0 = -1e30f, mx1 = -1e30f;
#pragma unroll
        for (int nt = 0; nt < 8; nt++) {
            mx0 = fmaxf(mx0, fmaxf(s[nt][0], s[nt][1]));
            mx1 = fmaxf(mx1, fmaxf(s[nt][2], s[nt][3]));
        }
        mx0 = fmaxf(mx0, __shfl_xor_sync(0xffffffffu, mx0, 1));
        mx0 = fmaxf(mx0, __shfl_xor_sync(0xffffffffu, mx0, 2));
        mx1 = fmaxf(mx1, __shfl_xor_sync(0xffffffffu, mx1, 1));
        mx1 = fmaxf(mx1, __shfl_xor_sync(0xffffffffu, mx1, 2));
        const float mn0 = fmaxf(m_0, mx0), mn1 = fmaxf(m_1, mx1);
        const float al0 = fex2((m_0 - mn0) * SCL2E);
        const float al1 = fex2((m_1 - mn1) * SCL2E);
        m_0 = mn0; m_1 = mn1;

        float sum0 = 0.f, sum1 = 0.f;
        unsigned aPh[4][4], aPl[4][4];
#pragma unroll
        for (int nt = 0; nt < 8; nt++) {
            float p0 = fex2((s[nt][0] - mn0) * SCL2E);
            float p1 = fex2((s[nt][1] - mn0) * SCL2E);
            float p2 = fex2((s[nt][2] - mn1) * SCL2E);
            float p3 = fex2((s[nt][3] - mn1) * SCL2E);
            sum0 += p0 + p1;
            sum1 += p2 + p3;
            float h0 = __bfloat162float(__float2bfloat16(p0));
            float h1 = __bfloat162float(__float2bfloat16(p1));
            float h2 = __bfloat162float(__float2bfloat16(p2));
            float h3 = __bfloat162float(__float2bfloat16(p3));
            const int kc = nt >> 1, hf = (nt & 1) * 2;
            aPh[kc][hf] = pack_bf2(p0, p1);
            aPh[kc][hf + 1] = pack_bf2(p2, p3);
            aPl[kc][hf] = pack_bf2(p0 - h0, p1 - h1);
            aPl[kc][hf + 1] = pack_bf2(p2 - h2, p3 - h3);
        }
        sum0 += __shfl_xor_sync(0xffffffffu, sum0, 1);
        sum0 += __shfl_xor_sync(0xffffffffu, sum0, 2);
        sum1 += __shfl_xor_sync(0xffffffffu, sum1, 1);
        sum1 += __shfl_xor_sync(0xffffffffu, sum1, 2);
        l_0 = l_0 * al0 + sum0;
        l_1 = l_1 * al1 + sum1;

#pragma unroll
        for (int i = 0; i < 16; i++) {
            o[i][0] *= al0; o[i][1] *= al0;
            o[i][2] *= al1; o[i][3] *= al1;
        }

        const int vrow0 = (lane & 7) + (((lane >> 3) & 1) << 3);
        const int vcbl = (lane >> 4) << 4;
#pragma unroll
        for (int kc = 0; kc < 4; kc++) {
            const int vr = kc * 16 + vrow0;
#pragma unroll
            for (int nb = 0; nb < 8; nb++) {
                unsigned vh_[4], vl_[4];
                const int vcb = nb * 32 + vcbl;
                LDSM_X4T(vh_, sV_h + sw256(vr, vcb));
                LDSM_X4T(vl_, sV_l + sw256(vr, vcb));
                mma16816(o[2 * nb], aPh[kc], vh_[0], vh_[1]);
                mma16816(o[2 * nb + 1], aPh[kc], vh_[2], vh_[3]);
                mma16816(o[2 * nb], aPh[kc], vl_[0], vl_[1]);
                mma16816(o[2 * nb + 1], aPh[kc], vl_[2], vl_[3]);
                mma16816(o[2 * nb], aPl[kc], vh_[0], vh_[1]);
                mma16816(o[2 * nb + 1], aPl[kc], vh_[2], vh_[3]);
            }
        }
        __syncthreads();
    }

    const float inv0 = 1.0f / l_0, inv1 = 1.0f / l_1;
    const int row0 = q0 + m0 + gp;
#pragma unroll
    for (int nt = 0; nt < 16; nt++) {
        const int col = h * 128 + nt * 8 + tig * 2;
        *(float2*)(O + (size_t)row0 * HIDW + col) =
            make_float2(o[nt][0] * inv0, o[nt][1] * inv0);
        *(float2*)(O + (size_t)(row0 + 8) * HIDW + col) =
            make_float2(o[nt][2] * inv1, o[nt][3] * inv1);
    }
}

// ---------------------------------------------------------------------------
// Fused rms + rope + bf16-split: warp-per-head, thread-owns-4-dims. No barriers.
// ---------------------------------------------------------------------------
__global__ __launch_bounds__(256) void fuse_qk_kernel(
    const float* __restrict__ Qb, const float* __restrict__ Kb,
    const float* __restrict__ EQb, const float* __restrict__ EKb,
    const float* __restrict__ IPKb,
    const float* __restrict__ nqw, const float* __restrict__ nkw,
    const float* __restrict__ naqw, const float* __restrict__ nakw,
    const float* __restrict__ nipq, const float* __restrict__ nipk,
    const float* __restrict__ cosT, const float* __restrict__ sinT,
    __nv_bfloat16* __restrict__ bh, __nv_bfloat16* __restrict__ bl)
{
    const int r = blockIdx.x;
    const int w = threadIdx.x >> 5, lane = threadIdx.x & 31;

    const float* src;
    const float* wv;
    size_t obase;
    int row_out;
    bool do_rope;

    if (r < 1536) {
        row_out = r; do_rope = true; obase = OFF_QF;
        if (r < 512) { src = EQb + (size_t)r * HIDW; wv = naqw; }
        else         { src = Qb + (size_t)(r - 512) * HIDW; wv = nqw; }
    } else if (r < 3072) {
        row_out = r - 1536; do_rope = true; obase = OFF_KF;
        if (row_out < 512) { src = EKb + (size_t)row_out * HIDW; wv = nakw; }
        else               { src = Kb + (size_t)(row_out - 512) * HIDW; wv = nkw; }
    } else if (r < 4096) {
        row_out = r - 3072; do_rope = false; obase = OFF_IPQ;
        src = Qb + (size_t)row_out * HIDW; wv = nipq;
    } else {
        row_out = r - 4096; do_rope = false; obase = OFF_IPK;
        src = IPKb + (size_t)row_out * HIDW; wv = nipk;
    }

    const int d4 = lane * 4;
    const float4 wvv = *(const float4*)(wv + d4);
    float4 cs = make_float4(0, 0, 0, 0), sn = cs;
    if (do_rope) {
        cs = *(const float4*)(cosT + row_out * DHW + d4);
        sn = *(const float4*)(sinT + row_out * DHW + d4);
    }
    obase += (size_t)row_out * HIDW + d4;

#pragma unroll
    for (int hi = 0; hi < 3; hi++) {
        const int h = hi * 8 + w;
        float4 x = *(const float4*)(src + h * DHW + d4);
        float v = x.x * x.x + x.y * x.y + x.z * x.z + x.w * x.w;
#pragma unroll
        for (int off = 16; off > 0; off >>= 1)
            v += __shfl_xor_sync(0xffffffffu, v, off);
        const float rinv = rsqrtf(v * (1.0f / 128.0f) + 1e-6f);
        float y0 = x.x * rinv * wvv.x;
        float y1 = x.y * rinv * wvv.y;
        float y2 = x.z * rinv * wvv.z;
        float y3 = x.w * rinv * wvv.w;
        if (do_rope) {
            float r0 = y0 * cs.x - y1 * sn.x;
            float r1 = y1 * cs.y + y0 * sn.y;
            float r2 = y2 * cs.z - y3 * sn.z;
            float r3 = y3 * cs.w + y2 * sn.w;
            y0 = r0; y1 = r1; y2 = r2; y3 = r3;
        }
        unsigned h01 = pack_bf2(y0, y1);
        unsigned h23 = pack_bf2(y2, y3);
        float f0 = __bfloat162float(__float2bfloat16(y0));
        float f1 = __bfloat162float(__float2bfloat16(y1));
        float f2 = __bfloat162float(__float2bfloat16(y2));
        float f3 = __bfloat162float(__float2bfloat16(y3));
        unsigned l01 = pack_bf2(y0 - f0, y1 - f1);
        unsigned l23 = pack_bf2(y2 - f2, y3 - f3);
        *(uint2*)(bh + obase + h * DHW) = make_uint2(h01, h23);
        *(uint2*)(bl + obase + h * DHW) = make_uint2(l01, l23);
    }
}

// ---------------------------------------------------------------------------
// Fused maskadd + AT bf16 splits (proven in R8). grid 1536, block 256.
// rows [0,512): AT enc -> ATE hi/lo ; rows [512,1536): AT img (+IPO) -> ATI.
// ---------------------------------------------------------------------------
__global__ __launch_bounds__(256) void fuse_at_kernel(
    const float* __restrict__ AT, const float* __restrict__ IPO,
    __nv_bfloat16* __restrict__ bh, __nv_bfloat16* __restrict__ bl)
{
    const int r = blockIdx.x;
    const float* arow = AT + (size_t)r * HIDW;
    size_t obase;
    const float* adder = nullptr;
    if (r < 512) {
        obase = OFF_ATE + (size_t)r * HIDW;
    } else {
        int i = r - 512;
        obase = OFF_ATI + (size_t)i * HIDW;
        int y = i >> 5, x = i & 31;
        if (y >= 8 && y < 24 && x >= 8 && x < 24)
            adder = IPO + (size_t)i * HIDW;
    }
    for (int c = threadIdx.x; c < HIDW; c += 256) {
        float v = arow[c];
        if (adder) v += adder[c];
        __nv_bfloat16 hi = __float2bfloat16(v);
        bh[obase + c] = hi;
        bl[obase + c] = __float2bfloat16(v - __bfloat162float(hi));
    }
}

// ---------------------------------------------------------------------------
extern "C" void kernel_launch(void* const* d_in, const int* in_sizes, int n_in,
                              void* d_out, int out_size)
{
    const float* hs    = (const float*)d_in[0];
    const float* enc   = (const float*)d_in[1];
    const float* ip    = (const float*)d_in[2];
    const float* cosT  = (const float*)d_in[3];
    const float* sinT  = (const float*)d_in[4];
    const float* Wq    = (const float*)d_in[5];
    const float* bq    = (const float*)d_in[6];
    const float* Wk    = (const float*)d_in[7];
    const float* bk    = (const float*)d_in[8];
    const float* Wv    = (const float*)d_in[9];
    const float* bv    = (const float*)d_in[10];
    const float* nqw   = (const float*)d_in[11];
    const float* nkw   = (const float*)d_in[12];
    const float* Wqa   = (const float*)d_in[13];
    const float* bqa   = (const float*)d_in[14];
    const float* Wka   = (const float*)d_in[15];
    const float* bka   = (const float*)d_in[16];
    const float* Wva   = (const float*)d_in[17];
    const float* bva   = (const float*)d_in[18];
    const float* naqw  = (const float*)d_in[19];
    const float* nakw  = (const float*)d_in[20];
    const float* Wout  = (const float*)d_in[21];
    const float* bout  = (const float*)d_in[22];
    const float* Waout = (const float*)d_in[23];
    const float* baout = (const float*)d_in[24];
    const float* Wkip  = (const float*)d_in[25];
    const float* bkip  = (const float*)d_in[26];
    const float* Wvip  = (const float*)d_in[27];
    const float* bvip  = (const float*)d_in[28];
    const float* nipq  = (const float*)d_in[29];
    const float* nipk  = (const float*)d_in[30];

    float* buf = nullptr;
    cudaGetSymbolAddress((void**)&buf, g_buf);
    __nv_bfloat16* bh = nullptr;
    __nv_bfloat16* bl = nullptr;
    cudaGetSymbolAddress((void**)&bh, g_bh);
    cudaGetSymbolAddress((void**)&bl, g_bl);

    float* Qb   = buf + (size_t)O_Q * HIDW;
    float* Kb   = buf + (size_t)O_K * HIDW;
    float* EQb  = buf + (size_t)O_EQ * HIDW;
    float* EKb  = buf + (size_t)O_EK * HIDW;
    float* IPKb = buf + (size_t)O_IPK * HIDW;
    float* ATb  = buf + (size_t)O_ATTN * HIDW;
    float* IPOb = buf + (size_t)O_IPOUT * HIDW;

    float* out_img = (float*)d_out;
    float* out_enc = (float*)d_out + (size_t)IMGN * HIDW;

    const int smem_gemm = 98304;   // 96 KB
    const int smem_fa   = 196608;
    cudaFuncSetAttribute(gemm_multi_kernel, cudaFuncAttributeMaxDynamicSharedMemorySize,
                         smem_gemm);
    cudaFuncSetAttribute(flash_kernel, cudaFuncAttributeMaxDynamicSharedMemorySize,
                         smem_fa);

    // ---- 0) split activations to bf16 hi/lo (small: ~19 MB) ----
    {
        SJobs js;
        js.njobs = 3;
        const float* srcs[3] = {hs, enc, ip};
        const size_t offs[3] = {OFF_HS, OFF_ENC, OFF_IP};
        const size_t ns[3]   = {3145728ull, 1572864ull, 147456ull};
        int blk = 0;
        for (int j = 0; j < 3; j++) {
            js.j[j].src = (const float4*)srcs[j];
            js.j[j].hi = (__nv_bfloat162*)(bh + offs[j]);
            js.j[j].lo = (__nv_bfloat162*)(bl + offs[j]);
            js.j[j].blk0 = blk;
            blk += (int)(ns[j] / 1024);
        }
        split_multi_kernel<<<blk, 256>>>(js);
    }

    // ---- 1) all 8 projections in one GEMM launch ----
    {
        GJobs gj;
        gj.njobs = 8;
        auto setj = [&](int i, size_t offA, const float* B, const float* bias,
                        float* C, __nv_bfloat16* Oh, __nv_bfloat16* Ol,
                        int M, int K, int& blk) {
            gj.j[i].Ah = bh + offA; gj.j[i].Al = bl + offA;
            gj.j[i].B = B; gj.j[i].bias = bias;
            gj.j[i].C = C; gj.j[i].Oh = Oh; gj.j[i].Ol = Ol;
            gj.j[i].K = K; gj.j[i].blk0 = blk;
            gj.j[i].mode = (Oh != nullptr) ? 1 : 0;
            blk += (M / 128) * 24;
        };
        int blk = 0;
        setj(0, OFF_HS, Wq, bq, Qb, nullptr, nullptr, IMGN, HIDW, blk);
        setj(1, OFF_HS, Wk, bk, Kb, nullptr, nullptr, IMGN, HIDW, blk);
        setj(2, OFF_HS, Wv, bv, nullptr,
             bh + OFF_VF + (size_t)TXTN * HIDW, bl + OFF_VF + (size_t)TXTN * HIDW,
             IMGN, HIDW, blk);
        setj(3, OFF_ENC, Wqa, bqa, EQb, nullptr, nullptr, TXTN, HIDW, blk);
        setj(4, OFF_ENC, Wka, bka, EKb, nullptr, nullptr, TXTN, HIDW, blk);
        setj(5, OFF_ENC, Wva, bva, nullptr,
             bh + OFF_VF, bl + OFF_VF, TXTN, HIDW, blk);
        setj(6, OFF_IP, Wkip, bkip, IPKb, nullptr, nullptr, 128, 1152, blk);
        setj(7, OFF_IP, Wvip, bvip, nullptr,
             bh + OFF_IPV, bl + OFF_IPV, 128, 1152, blk);
        gemm_multi_kernel<<<blk, 256, smem_gemm>>>(gj);
    }

    // ---- 2) fused rms + rope + split ----
    fuse_qk_kernel<<<4224, 256>>>(
        Qb, Kb, EQb, EKb, IPKb, nqw, nkw, naqw, nakw, nipq, nipk,
        cosT, sinT, bh, bl);

    // ---- 3) flash attention ----
    flash_kernel<<<dim3(S_ALL / 128, NHW), 256, smem_fa>>>(
        bh + OFF_QF, bl + OFF_QF, bh + OFF_KF, bl + OFF_KF,
        bh + OFF_VF, bl + OFF_VF, ATb, S_ALL);
    flash_kernel<<<dim3(IMGN / 128, NHW), 256, smem_fa>>>(
        bh + OFF_IPQ, bl + OFF_IPQ, bh + OFF_IPK, bl + OFF_IPK,
        bh + OFF_IPV, bl + OFF_IPV, IPOb, 128);

    // ---- 4) fused maskadd + AT splits ----
    fuse_at_kernel<<<S_ALL, 256>>>(ATb, IPOb, bh, bl);

    // ---- 5) output projections in one GEMM launch ----
    {
        GJobs gj;
        gj.njobs = 2;
        int blk = 0;
        gj.j[0].Ah = bh + OFF_ATI; gj.j[0].Al = bl + OFF_ATI;
        gj.j[0].B = Wout; gj.j[0].bias = bout; gj.j[0].C = out_img;
        gj.j[0].Oh = nullptr; gj.j[0].Ol = nullptr;
        gj.j[0].K = HIDW; gj.j[0].blk0 = blk; gj.j[0].mode = 0;
        blk += (IMGN / 128) * 24;
        gj.j[1].Ah = bh + OFF_ATE; gj.j[1].Al = bl + OFF_ATE;
        gj.j[1].B = Waout; gj.j[1].bias = baout; gj.j[1].C = out_enc;
        gj.j[1].Oh = nullptr; gj.j[1].Ol = nullptr;
        gj.j[1].K = HIDW; gj.j[1].blk0 = blk; gj.j[1].mode = 0;
        blk += (TXTN / 128) * 24;
        gemm_multi_kernel<<<blk, 256, smem_gemm>>>(gj);
    }
}